// round 13
// baseline (speedup 1.0000x reference)
#include <cuda_runtime.h>
#include <cuda_bf16.h>
#include <cstdint>
#include <math.h>

// ============================ problem constants ============================
namespace {
constexpr int Bb=128, Ll=50, Nn=Bb*Ll, Dd=64, Kc=1024;
constexpr int LDK = 72;           // bf16 smem row stride
constexpr int VQS = 4;            // VQ codebook splits

// attn grid: 46 row blocks x 6 splits + 4 row blocks x 5 splits = 296 = 2*148
constexpr int ATTN_GRID = 296;

// attn smem (bf16 elements)
constexpr int KS_OFF = 128*LDK;
constexpr int VS_OFF = KS_OFF + 2*128*LDK;
constexpr int SM_ELEMS = VS_OFF + 2*128*LDK;
constexpr int RS_OFF_B = SM_ELEMS*2;
constexpr int ATTN_SMEM_B = RS_OFF_B + 1024;   // 93184 B

// vq smem
constexpr int VQ_C_OFF  = 2*128*LDK;
constexpr int VQ_CN_B   = (VQ_C_OFF + 2*128*LDK)*2;
constexpr int VQ_RED_B  = VQ_CN_B + 256*4;
constexpr int VQ_SMEM_B = VQ_RED_B + 2*128*4*2;  // ~77KB (2 CTAs/SM fit)

// qkv smem (bf16 elements): H0h,H0l [128][LDK], Wh,Wl [64][LDK]
constexpr int QKV_H0L  = 128*LDK;
constexpr int QKV_WH   = 2*128*LDK;
constexpr int QKV_WL   = QKV_WH + 64*LDK;
constexpr int QKV_SMEM_B = (QKV_WL + 64*LDK)*2;   // 55296 B
}

// ============================ scratch (device globals) =====================
__device__ float g_h [Nn*Dd];
__device__ float g_acc[Nn*Dd];     // attention numerator (atomic accumulated)
__device__ float g_rsum[Nn];       // sum of u (atomic accumulated)
__device__ float g_denom[Bb];
__device__ float g_cnorm[Kc];
__device__ float g_vcolsum[Dd];    // atomic accumulated
__device__ float g_bval[VQS][Nn];
__device__ int   g_bidx[VQS][Nn];
__device__ __nv_bfloat16 g_qh[Nn*Dd];
__device__ __nv_bfloat16 g_kh[Nn*Dd];
__device__ __nv_bfloat16 g_vh[Nn*Dd];
__device__ __nv_bfloat16 g_hh[Nn*Dd];
__device__ __nv_bfloat16 g_hl[Nn*Dd];
__device__ __nv_bfloat16 g_cbh[Kc*Dd];
__device__ __nv_bfloat16 g_cbl[Kc*Dd];

// ============================ asm helpers ==================================
__device__ __forceinline__ uint32_t smaddr(const void* p) {
    return (uint32_t)__cvta_generic_to_shared(p);
}
__device__ __forceinline__ void ldsm_x4(uint32_t a, uint32_t& r0, uint32_t& r1,
                                        uint32_t& r2, uint32_t& r3) {
    asm volatile("ldmatrix.sync.aligned.m8n8.x4.shared.b16 {%0,%1,%2,%3},[%4];"
                 : "=r"(r0), "=r"(r1), "=r"(r2), "=r"(r3) : "r"(a));
}
__device__ __forceinline__ void ldsm_x4t(uint32_t a, uint32_t& r0, uint32_t& r1,
                                         uint32_t& r2, uint32_t& r3) {
    asm volatile("ldmatrix.sync.aligned.m8n8.x4.trans.shared.b16 {%0,%1,%2,%3},[%4];"
                 : "=r"(r0), "=r"(r1), "=r"(r2), "=r"(r3) : "r"(a));
}
__device__ __forceinline__ void mma16816(float c[4], const uint32_t a[4],
                                         const uint32_t b0, const uint32_t b1) {
    asm volatile("mma.sync.aligned.m16n8k16.row.col.f32.bf16.bf16.f32 "
                 "{%0,%1,%2,%3},{%4,%5,%6,%7},{%8,%9},{%0,%1,%2,%3};"
                 : "+f"(c[0]), "+f"(c[1]), "+f"(c[2]), "+f"(c[3])
                 : "r"(a[0]), "r"(a[1]), "r"(a[2]), "r"(a[3]), "r"(b0), "r"(b1));
}
__device__ __forceinline__ void cpa16(uint32_t dst, const void* src) {
    asm volatile("cp.async.cg.shared.global [%0],[%1],16;" :: "r"(dst), "l"(src));
}
__device__ __forceinline__ uint32_t packbf2(float lo, float hi) {
    __nv_bfloat162 v = __float22bfloat162_rn(make_float2(lo, hi));
    return *(uint32_t*)&v;
}

// ---------------------------------------------------------------------------
// 1. prep: codebook hi/lo split + cnorm (blocks 0..63), denom + vcolsum zero
//    (block 64), zero g_acc (65..164), zero g_rsum (165..171)
// ---------------------------------------------------------------------------
__global__ void prep_kernel(const int* __restrict__ masks,
                            const float* __restrict__ cb) {
    const int b = blockIdx.x, tid = threadIdx.x;
    if (b < 64) {
        int i = b*256 + tid;              // float4 index into cb
        float4 c = ((const float4*)cb)[i];
        float cv[4] = {c.x, c.y, c.z, c.w};
        #pragma unroll
        for (int j = 0; j < 4; j++) {
            __nv_bfloat16 h = __float2bfloat16(cv[j]);
            g_cbh[i*4 + j] = h;
            g_cbl[i*4 + j] = __float2bfloat16(cv[j] - __bfloat162float(h));
        }
        float part = fmaf(c.x,c.x, fmaf(c.y,c.y, fmaf(c.z,c.z, c.w*c.w)));
        #pragma unroll
        for (int off = 1; off <= 8; off <<= 1)
            part += __shfl_xor_sync(0xffffffffu, part, off);
        if ((tid & 15) == 0) g_cnorm[i >> 4] = part;
    } else if (b == 64) {
        if (tid < Bb) {
            float s = 0.0f;
            for (int l = 0; l < Ll; l++) s += (masks[tid*Ll + l] >= 1) ? 1.0f : 0.0f;
            g_denom[tid] = s;
        } else if (tid < Bb + Dd) {
            g_vcolsum[tid - Bb] = 0.0f;
        }
    } else if (b < 165) {
        float4 z = make_float4(0.f, 0.f, 0.f, 0.f);
        #pragma unroll
        for (int j = 0; j < 4; j++)
            ((float4*)g_acc)[(b-65)*1024 + j*256 + tid] = z;
    } else {
        int f4 = (b-165)*256 + tid;
        if (f4 < Nn/4)
            ((float4*)g_rsum)[f4] = make_float4(0.f, 0.f, 0.f, 0.f);
    }
}

// ---------------------------------------------------------------------------
// 2. fused embed + tensor-core QKV; one weight matrix per blockIdx.y
// ---------------------------------------------------------------------------
__global__ void __launch_bounds__(256) qkv_tc_kernel(
    const int* __restrict__ ids, const int* __restrict__ masks,
    const float* __restrict__ emb,
    const float* __restrict__ Wq, const float* __restrict__ bq,
    const float* __restrict__ Wk, const float* __restrict__ bk,
    const float* __restrict__ Wv, const float* __restrict__ bv)
{
    extern __shared__ __nv_bfloat16 qsm[];
    __nv_bfloat16* H0h = qsm;
    __nv_bfloat16* H0l = qsm + QKV_H0L;
    __nv_bfloat16* Wh  = qsm + QKV_WH;
    __nv_bfloat16* Wl  = qsm + QKV_WL;

    const int tid = threadIdx.x, lane = tid & 31, wid = tid >> 5;
    const int wm = wid >> 1, wn = wid & 1;
    const int q0 = blockIdx.x * 128;
    const int m  = blockIdx.y;

    const float* Wsel = (m == 0) ? Wq : (m == 1) ? Wk : Wv;
    const float* bsel = (m == 0) ? bq : (m == 1) ? bk : bv;
    __nv_bfloat16* osel = (m == 0) ? g_qh : (m == 1) ? g_kh : g_vh;

    // embed gather + mask + hi/lo split, straight into smem
    {
        int r = tid >> 1, half = tid & 1;
        int n = q0 + r;
        float mval = (masks[n] >= 1) ? 1.0f : 0.0f;
        const float4* src = (const float4*)(emb + (size_t)ids[n] * Dd) + half*8;
        #pragma unroll
        for (int j = 0; j < 8; j++) {
            float4 v = src[j];
            float vv[4] = {v.x*mval, v.y*mval, v.z*mval, v.w*mval};
            float hi[4], lo[4];
            #pragma unroll
            for (int e = 0; e < 4; e++) {
                __nv_bfloat16 h = __float2bfloat16(vv[e]);
                hi[e] = __bfloat162float(h);
                lo[e] = vv[e] - hi[e];
            }
            int col = half*32 + j*4;
            *(uint32_t*)&H0h[r*LDK + col]     = packbf2(hi[0], hi[1]);
            *(uint32_t*)&H0h[r*LDK + col + 2] = packbf2(hi[2], hi[3]);
            *(uint32_t*)&H0l[r*LDK + col]     = packbf2(lo[0], lo[1]);
            *(uint32_t*)&H0l[r*LDK + col + 2] = packbf2(lo[2], lo[3]);
        }
    }
    // weight load (no sync needed yet; W region disjoint from H0)
    for (int idx = tid; idx < 4096; idx += 256) {
        int k = idx >> 6, n = idx & 63;
        float w = Wsel[idx];
        __nv_bfloat16 h = __float2bfloat16(w);
        Wh[k*LDK + n] = h;
        Wl[k*LDK + n] = __float2bfloat16(w - __bfloat162float(h));
    }
    __syncthreads();

    uint32_t ah[2][4][4], al[2][4][4];
    #pragma unroll
    for (int mi = 0; mi < 2; mi++)
        #pragma unroll
        for (int ks = 0; ks < 4; ks++) {
            int row = wm*32 + mi*16 + (lane & 15);
            ldsm_x4(smaddr(H0h + row*LDK + ks*16 + (lane >> 4)*8),
                    ah[mi][ks][0], ah[mi][ks][1], ah[mi][ks][2], ah[mi][ks][3]);
            ldsm_x4(smaddr(H0l + row*LDK + ks*16 + (lane >> 4)*8),
                    al[mi][ks][0], al[mi][ks][1], al[mi][ks][2], al[mi][ks][3]);
        }

    float c[2][4][4] = {};
    #pragma unroll
    for (int ks = 0; ks < 4; ks++) {
        int kr = ks*16 + (lane & 15);
        #pragma unroll
        for (int njp = 0; njp < 2; njp++) {
            uint32_t bh[4], bl[4];
            uint32_t colg = (wn*4 + njp*2 + (lane >> 4))*8;
            ldsm_x4t(smaddr(Wh + kr*LDK + colg), bh[0], bh[1], bh[2], bh[3]);
            ldsm_x4t(smaddr(Wl + kr*LDK + colg), bl[0], bl[1], bl[2], bl[3]);
            #pragma unroll
            for (int mi = 0; mi < 2; mi++) {
                mma16816(c[mi][njp*2],   ah[mi][ks], bh[0], bh[1]);
                mma16816(c[mi][njp*2],   al[mi][ks], bh[0], bh[1]);
                mma16816(c[mi][njp*2],   ah[mi][ks], bl[0], bl[1]);
                mma16816(c[mi][njp*2+1], ah[mi][ks], bh[2], bh[3]);
                mma16816(c[mi][njp*2+1], al[mi][ks], bh[2], bh[3]);
                mma16816(c[mi][njp*2+1], ah[mi][ks], bl[2], bl[3]);
            }
        }
    }

    float csum[4][2];
    #pragma unroll
    for (int nj = 0; nj < 4; nj++) { csum[nj][0] = 0.0f; csum[nj][1] = 0.0f; }

    #pragma unroll
    for (int mi = 0; mi < 2; mi++)
        #pragma unroll
        for (int nj = 0; nj < 4; nj++) {
            int col0 = wn*32 + nj*8 + (lane & 3)*2;
            float b0 = bsel[col0], b1 = bsel[col0 + 1];
            float c0 = c[mi][nj][0] + b0, c1 = c[mi][nj][1] + b1;
            float c2 = c[mi][nj][2] + b0, c3 = c[mi][nj][3] + b1;
            int r0 = q0 + wm*32 + mi*16 + (lane >> 2);
            *(uint32_t*)&osel[r0*64 + col0]       = packbf2(c0, c1);
            *(uint32_t*)&osel[(r0 + 8)*64 + col0] = packbf2(c2, c3);
            if (m == 2) { csum[nj][0] += c0 + c2; csum[nj][1] += c1 + c3; }
        }

    if (m == 2) {
        #pragma unroll
        for (int nj = 0; nj < 4; nj++) {
            #pragma unroll
            for (int off = 4; off <= 16; off <<= 1) {
                csum[nj][0] += __shfl_xor_sync(0xffffffffu, csum[nj][0], off);
                csum[nj][1] += __shfl_xor_sync(0xffffffffu, csum[nj][1], off);
            }
            if (lane < 4) {
                int col = wn*32 + nj*8 + lane*2;
                atomicAdd(&g_vcolsum[col],     csum[nj][0]);
                atomicAdd(&g_vcolsum[col + 1], csum[nj][1]);
            }
        }
    }
}

// ---------------------------------------------------------------------------
// 3. tensor-core attention partials (expm1 form); balanced grid of 296 CTAs:
//    row blocks 0..45 -> 6 splits (9/9/8/8/8/8 tiles), 46..49 -> 5 splits
//    (10 tiles each). Atomic accumulation into g_acc / g_rsum.
// ---------------------------------------------------------------------------
__global__ void __launch_bounds__(256) attn_tc_kernel() {
    extern __shared__ __nv_bfloat16 sm[];
    __nv_bfloat16* Qs = sm;
    __nv_bfloat16* Ks[2] = { sm + KS_OFF, sm + KS_OFF + 128*LDK };
    __nv_bfloat16* Vs[2] = { sm + VS_OFF, sm + VS_OFF + 128*LDK };
    float* rsred = (float*)((char*)sm + RS_OFF_B);

    const int tid = threadIdx.x, lane = tid & 31, wid = tid >> 5;
    const int wm = wid >> 1, wn = wid & 1;

    int rb, base_t, tps;
    {
        int id = blockIdx.x;
        if (id < 276) {
            rb = id / 6;
            int sp = id - rb*6;
            base_t = sp*8 + (sp < 2 ? sp : 2);
            tps    = 8 + (sp < 2 ? 1 : 0);
        } else {
            int j = id - 276;
            rb = 46 + j / 5;
            int sp = j % 5;
            base_t = sp * 10;
            tps    = 10;
        }
    }
    const int q0 = rb * 128;
    const int kvbase = base_t * 128;

    for (int c = tid; c < 1024; c += 256) {
        int r = c >> 3, g = c & 7;
        cpa16(smaddr(Qs + r*LDK + g*8), g_qh + (q0 + r)*64 + g*8);
        cpa16(smaddr(Ks[0] + r*LDK + g*8), g_kh + (kvbase + r)*64 + g*8);
        cpa16(smaddr(Vs[0] + r*LDK + g*8), g_vh + (kvbase + r)*64 + g*8);
    }
    asm volatile("cp.async.commit_group;");
    asm volatile("cp.async.wait_group 0;");
    __syncthreads();

    uint32_t qa[2][4][4];
    #pragma unroll
    for (int mi = 0; mi < 2; mi++)
        #pragma unroll
        for (int ks = 0; ks < 4; ks++) {
            int row = wm*32 + mi*16 + (lane & 15);
            ldsm_x4(smaddr(Qs + row*LDK + ks*16 + (lane >> 4)*8),
                    qa[mi][ks][0], qa[mi][ks][1], qa[mi][ks][2], qa[mi][ks][3]);
        }

    float o[2][8][4] = {};
    float rs[2][2]   = {};

    for (int t = 0; t < tps; t++) {
        const int buf = t & 1;
        if (t + 1 < tps) {
            const int kv1 = kvbase + (t+1)*128;
            __nv_bfloat16* Kd = Ks[buf^1];
            __nv_bfloat16* Vd = Vs[buf^1];
            for (int c = tid; c < 1024; c += 256) {
                int r = c >> 3, g = c & 7;
                cpa16(smaddr(Kd + r*LDK + g*8), g_kh + (kv1 + r)*64 + g*8);
                cpa16(smaddr(Vd + r*LDK + g*8), g_vh + (kv1 + r)*64 + g*8);
            }
        }
        asm volatile("cp.async.commit_group;");
        asm volatile("cp.async.wait_group 1;");
        __syncthreads();

        float c[2][8][4] = {};
        const __nv_bfloat16* Kb = Ks[buf];
        #pragma unroll
        for (int nj = 0; nj < 8; nj++) {
            uint32_t kb[4][2];
            int r = wn*64 + nj*8 + (lane & 7);
            ldsm_x4(smaddr(Kb + r*LDK + (lane >> 3)*8),
                    kb[0][0], kb[0][1], kb[1][0], kb[1][1]);
            ldsm_x4(smaddr(Kb + r*LDK + 32 + (lane >> 3)*8),
                    kb[2][0], kb[2][1], kb[3][0], kb[3][1]);
            #pragma unroll
            for (int mi = 0; mi < 2; mi++)
                #pragma unroll
                for (int ks = 0; ks < 4; ks++)
                    mma16816(c[mi][nj], qa[mi][ks], kb[ks][0], kb[ks][1]);
        }

        #pragma unroll
        for (int mi = 0; mi < 2; mi++)
            #pragma unroll
            for (int nj = 0; nj < 8; nj++)
                #pragma unroll
                for (int e = 0; e < 4; e++) {
                    float x = c[mi][nj][e] * 0.125f;
                    float u = x * (1.0f + x * (0.5f + x * 0.16666667f));
                    c[mi][nj][e] = u;
                    rs[mi][e >> 1] += u;
                }

        const __nv_bfloat16* Vb = Vs[buf];
        #pragma unroll
        for (int ss = 0; ss < 4; ss++) {
            uint32_t a[2][4];
            #pragma unroll
            for (int mi = 0; mi < 2; mi++) {
                const float* u0 = c[mi][2*ss];
                const float* u1 = c[mi][2*ss + 1];
                a[mi][0] = packbf2(u0[0], u0[1]);
                a[mi][1] = packbf2(u0[2], u0[3]);
                a[mi][2] = packbf2(u1[0], u1[1]);
                a[mi][3] = packbf2(u1[2], u1[3]);
            }
            int kr = wn*64 + ss*16 + (lane & 15);
            #pragma unroll
            for (int jd = 0; jd < 8; jd += 2) {
                uint32_t b[4];
                ldsm_x4t(smaddr(Vb + kr*LDK + (jd + (lane >> 4))*8),
                         b[0], b[1], b[2], b[3]);
                #pragma unroll
                for (int mi = 0; mi < 2; mi++) {
                    mma16816(o[mi][jd],     a[mi], b[0], b[1]);
                    mma16816(o[mi][jd + 1], a[mi], b[2], b[3]);
                }
            }
        }
        __syncthreads();
    }

    #pragma unroll
    for (int mi = 0; mi < 2; mi++)
        #pragma unroll
        for (int h = 0; h < 2; h++) {
            float v = rs[mi][h];
            v += __shfl_xor_sync(0xffffffffu, v, 1);
            v += __shfl_xor_sync(0xffffffffu, v, 2);
            if ((lane & 3) == 0) {
                int row = wm*32 + mi*16 + h*8 + (lane >> 2);
                rsred[wn*128 + row] = v;
            }
        }

    float* Ored = (float*)sm;  // [128][66] floats
    if (wn == 1) {
        #pragma unroll
        for (int mi = 0; mi < 2; mi++)
            #pragma unroll
            for (int jd = 0; jd < 8; jd++) {
                int r0 = wm*32 + mi*16 + (lane >> 2);
                int col = jd*8 + (lane & 3)*2;
                float* p = Ored + r0*66 + col;
                p[0] = o[mi][jd][0]; p[1] = o[mi][jd][1];
                p = Ored + (r0 + 8)*66 + col;
                p[0] = o[mi][jd][2]; p[1] = o[mi][jd][3];
            }
    }
    __syncthreads();
    if (tid < 128)
        atomicAdd(&g_rsum[q0 + tid], rsred[tid] + rsred[128 + tid]);
    if (wn == 0) {
        #pragma unroll
        for (int mi = 0; mi < 2; mi++)
            #pragma unroll
            for (int jd = 0; jd < 8; jd++) {
                int r0 = wm*32 + mi*16 + (lane >> 2);
                int col = jd*8 + (lane & 3)*2;
                float2 p0 = *(float2*)(Ored + r0*66 + col);
                float2 p1 = *(float2*)(Ored + (r0 + 8)*66 + col);
                atomicAdd(&g_acc[(q0 + r0)*64 + col],     o[mi][jd][0] + p0.x);
                atomicAdd(&g_acc[(q0 + r0)*64 + col + 1], o[mi][jd][1] + p0.y);
                atomicAdd(&g_acc[(q0 + r0 + 8)*64 + col],     o[mi][jd][2] + p1.x);
                atomicAdd(&g_acc[(q0 + r0 + 8)*64 + col + 1], o[mi][jd][3] + p1.y);
            }
    }
}

// ---------------------------------------------------------------------------
// 4. combine: h = (vcolsum + acc) / (Nn + rsum); writes g_h + g_hh/g_hl
//    (200 CTAs x 256 threads; one 32-row quarter block per CTA)
// ---------------------------------------------------------------------------
__global__ void __launch_bounds__(256) combine_kernel() {
    __shared__ float rssm[32], vcol[64];
    const int tid = threadIdx.x;
    const int r0 = blockIdx.x * 32;     // 32 rows per CTA
    if (tid < 32) rssm[tid] = (float)Nn + g_rsum[r0 + tid];
    else if (tid < 96) vcol[tid - 32] = g_vcolsum[tid - 32];
    __syncthreads();
    #pragma unroll
    for (int it = 0; it < 2; it++) {
        int i = it*256 + tid;          // float4 index in [0, 512)
        int r = i >> 4, f = i & 15;
        float4 a = ((const float4*)g_acc)[(r0 + r)*16 + f];
        float4 vc = *(const float4*)&vcol[f*4];
        float inv = 1.0f / rssm[r];
        float hv[4] = {(a.x+vc.x)*inv, (a.y+vc.y)*inv, (a.z+vc.z)*inv, (a.w+vc.w)*inv};
        ((float4*)g_h)[(r0 + r)*16 + f] = make_float4(hv[0], hv[1], hv[2], hv[3]);
        float hi[4], lo[4];
        #pragma unroll
        for (int e = 0; e < 4; e++) {
            __nv_bfloat16 h = __float2bfloat16(hv[e]);
            hi[e] = __bfloat162float(h);
            lo[e] = hv[e] - hi[e];
        }
        int gi = (r0 + r)*64 + f*4;
        *(uint2*)&g_hh[gi] = make_uint2(packbf2(hi[0],hi[1]), packbf2(hi[2],hi[3]));
        *(uint2*)&g_hl[gi] = make_uint2(packbf2(lo[0],lo[1]), packbf2(lo[2],lo[3]));
    }
}

// ---------------------------------------------------------------------------
// 5. tensor-core VQ argmin (4-way codebook split, 2 CTAs/SM, pure bf16 path)
// ---------------------------------------------------------------------------
__global__ void __launch_bounds__(256, 2) vq_tc_kernel() {
    extern __shared__ __nv_bfloat16 vsm[];
    __nv_bfloat16* Fh = vsm;
    __nv_bfloat16* Fl = vsm + 128*LDK;
    __nv_bfloat16* Ch = vsm + VQ_C_OFF;
    __nv_bfloat16* Cl = vsm + VQ_C_OFF + 128*LDK;
    float* cns  = (float*)((char*)vsm + VQ_CN_B);    // 256 floats
    float* redv = (float*)((char*)vsm + VQ_RED_B);   // 256 floats (+ints after)
    int*   redi = (int*)(redv + 256);

    const int tid = threadIdx.x, lane = tid & 31, wid = tid >> 5;
    const int wm = wid >> 1, wn = wid & 1;
    const int q0 = blockIdx.x * 128;
    const int sy = blockIdx.y;
    const int kbase = sy * (Kc/VQS);     // 256 codes per split

    // issue F + cnorm + C tile 0 loads in one batch
    for (int c = tid; c < 1024; c += 256) {
        int r = c >> 3, g = c & 7;
        cpa16(smaddr(Fh + r*LDK + g*8), g_hh + (q0 + r)*64 + g*8);
        cpa16(smaddr(Fl + r*LDK + g*8), g_hl + (q0 + r)*64 + g*8);
        cpa16(smaddr(Ch + r*LDK + g*8), g_cbh + kbase*64 + r*64 + g*8);
        cpa16(smaddr(Cl + r*LDK + g*8), g_cbl + kbase*64 + r*64 + g*8);
    }
    if (tid < 64) cpa16(smaddr(cns + tid*4), g_cnorm + kbase + tid*4);
    asm volatile("cp.async.commit_group;");
    asm volatile("cp.async.wait_group 0;");
    __syncthreads();

    uint32_t fha[2][4][4], fla[2][4][4];
    #pragma unroll
    for (int mi = 0; mi < 2; mi++)
        #pragma unroll
        for (int ks = 0; ks < 4; ks++) {
            int row = wm*32 + mi*16 + (lane & 15);
            ldsm_x4(smaddr(Fh + row*LDK + ks*16 + (lane >> 4)*8),
                    fha[mi][ks][0], fha[mi][ks][1], fha[mi][ks][2], fha[mi][ks][3]);
            ldsm_x4(smaddr(Fl + row*LDK + ks*16 + (lane >> 4)*8),
                    fla[mi][ks][0], fla[mi][ks][1], fla[mi][ks][2], fla[mi][ks][3]);
        }

    float best[2][2];
    int   bidx[2][2];
    #pragma unroll
    for (int mi = 0; mi < 2; mi++)
        #pragma unroll
        for (int h = 0; h < 2; h++) { best[mi][h] = 3.4e38f; bidx[mi][h] = 0; }

    for (int t = 0; t < Kc/VQS/128; t++) {   // 2 tiles
        if (t == 1) {
            __syncthreads();
            const int c0 = (kbase + 128)*64;
            for (int c = tid; c < 1024; c += 256) {
                int r = c >> 3, g = c & 7;
                cpa16(smaddr(Ch + r*LDK + g*8), g_cbh + c0 + r*64 + g*8);
                cpa16(smaddr(Cl + r*LDK + g*8), g_cbl + c0 + r*64 + g*8);
            }
            asm volatile("cp.async.commit_group;");
            asm volatile("cp.async.wait_group 0;");
            __syncthreads();
        }

        float c[2][8][4] = {};
        #pragma unroll
        for (int nj = 0; nj < 8; nj++) {
            uint32_t chb[4][2], clb[4][2];
            int r = wn*64 + nj*8 + (lane & 7);
            ldsm_x4(smaddr(Ch + r*LDK + (lane >> 3)*8),
                    chb[0][0], chb[0][1], chb[1][0], chb[1][1]);
            ldsm_x4(smaddr(Ch + r*LDK + 32 + (lane >> 3)*8),
                    chb[2][0], chb[2][1], chb[3][0], chb[3][1]);
            ldsm_x4(smaddr(Cl + r*LDK + (lane >> 3)*8),
                    clb[0][0], clb[0][1], clb[1][0], clb[1][1]);
            ldsm_x4(smaddr(Cl + r*LDK + 32 + (lane >> 3)*8),
                    clb[2][0], clb[2][1], clb[3][0], clb[3][1]);
            #pragma unroll
            for (int mi = 0; mi < 2; mi++)
                #pragma unroll
                for (int ks = 0; ks < 4; ks++) {
                    mma16816(c[mi][nj], fha[mi][ks], chb[ks][0], chb[ks][1]);
                    mma16816(c[mi][nj], fla[mi][ks], chb[ks][0], chb[ks][1]);
                    mma16816(c[mi][nj], fha[mi][ks], clb[ks][0], clb[ks][1]);
                }
        }

        // ascending col order per thread -> '<' keeps first (lowest) index
        #pragma unroll
        for (int mi = 0; mi < 2; mi++)
            #pragma unroll
            for (int nj = 0; nj < 8; nj++)
                #pragma unroll
                for (int e = 0; e < 4; e++) {
                    int lcol = t*128 + wn*64 + nj*8 + (lane & 3)*2 + (e & 1);
                    float d2 = cns[lcol] - 2.0f * c[mi][nj][e];
                    int h = e >> 1;
                    if (d2 < best[mi][h]) { best[mi][h] = d2; bidx[mi][h] = kbase + lcol; }
                }
    }

    #pragma unroll
    for (int mi = 0; mi < 2; mi++)
        #pragma unroll
        for (int h = 0; h < 2; h++) {
            float v = best[mi][h]; int ix = bidx[mi][h];
            #pragma unroll
            for (int off = 1; off <= 2; off <<= 1) {
                float v2 = __shfl_xor_sync(0xffffffffu, v, off);
                int   i2 = __shfl_xor_sync(0xffffffffu, ix, off);
                if (v2 < v || (v2 == v && i2 < ix)) { v = v2; ix = i2; }
            }
            if ((lane & 3) == 0) {
                int row = wm*32 + mi*16 + h*8 + (lane >> 2);
                redv[wn*128 + row] = v;
                redi[wn*128 + row] = ix;
            }
        }
    __syncthreads();
    if (tid < 128) {
        float v0 = redv[tid], v1 = redv[128 + tid];
        int   i0 = redi[tid], i1 = redi[128 + tid];
        bool take1 = (v1 < v0) || (v1 == v0 && i1 < i0);
        g_bval[sy][q0 + tid] = take1 ? v1 : v0;
        g_bidx[sy][q0 + tid] = take1 ? i1 : i0;
    }
}

// ---------------------------------------------------------------------------
// 6. merge VQ splits + per-batch means + final projection
//    (256 threads: 4 l-groups x 64 dims, smem reduce)
// ---------------------------------------------------------------------------
__global__ void __launch_bounds__(256) final_kernel(
    const float* __restrict__ cb, const float* __restrict__ W_enc,
    const float* __restrict__ b_enc, float* __restrict__ out)
{
    const int b = blockIdx.x, tid = threadIdx.x;
    const int d = tid & 63, grp = tid >> 6;    // 4 groups of 64
    __shared__ float sv[4*64], sh2[4*64], x[2*Dd];

    float vs = 0.0f, hs = 0.0f;
    for (int l = grp; l < Ll; l += 4) {
        int n = b*Ll + l;
        // splits have strictly increasing index ranges; strict '<' scan in
        // split order keeps the overall first-index minimum
        float bv = g_bval[0][n]; int bi = g_bidx[0][n];
        #pragma unroll
        for (int sp = 1; sp < VQS; sp++) {
            float v = g_bval[sp][n];
            if (v < bv) { bv = v; bi = g_bidx[sp][n]; }
        }
        vs += cb[(size_t)bi*Dd + d];
        hs += g_h[n*Dd + d];
    }
    sv[grp*64 + d] = vs;
    sh2[grp*64 + d] = hs;
    __syncthreads();
    if (tid < 64) {
        float den = g_denom[b];
        float v  = sv[tid] + sv[64 + tid] + sv[128 + tid] + sv[192 + tid];
        float hh = sh2[tid] + sh2[64 + tid] + sh2[128 + tid] + sh2[192 + tid];
        x[tid]      = v / den;
        x[Dd + tid] = hh / (den + 1e-9f);
    }
    __syncthreads();
    if (tid < 64) {
        float a0 = b_enc[d], a1 = 0.f, a2 = 0.f, a3 = 0.f;
        #pragma unroll 8
        for (int i = 0; i < 2*Dd; i += 4) {
            a0 = fmaf(x[i],     W_enc[i*Dd + d],       a0);
            a1 = fmaf(x[i + 1], W_enc[(i + 1)*Dd + d], a1);
            a2 = fmaf(x[i + 2], W_enc[(i + 2)*Dd + d], a2);
            a3 = fmaf(x[i + 3], W_enc[(i + 3)*Dd + d], a3);
        }
        out[b*Dd + d] = (a0 + a1) + (a2 + a3);
    }
}

// ---------------------------------------------------------------------------
extern "C" void kernel_launch(void* const* d_in, const int* in_sizes, int n_in,
                              void* d_out, int out_size) {
    const int*   ids   = (const int*)d_in[0];
    const int*   masks = (const int*)d_in[1];
    const float* emb   = (const float*)d_in[2];
    const float* cb    = (const float*)d_in[3];
    const float* Wq    = (const float*)d_in[4];
    const float* bq    = (const float*)d_in[5];
    const float* Wk    = (const float*)d_in[6];
    const float* bk    = (const float*)d_in[7];
    const float* Wv    = (const float*)d_in[8];
    const float* bv    = (const float*)d_in[9];
    const float* W_enc = (const float*)d_in[10];
    const float* b_enc = (const float*)d_in[11];
    float* out = (float*)d_out;

    cudaFuncSetAttribute((const void*)qkv_tc_kernel,
                         cudaFuncAttributeMaxDynamicSharedMemorySize, QKV_SMEM_B);
    cudaFuncSetAttribute((const void*)attn_tc_kernel,
                         cudaFuncAttributeMaxDynamicSharedMemorySize, ATTN_SMEM_B);
    cudaFuncSetAttribute((const void*)vq_tc_kernel,
                         cudaFuncAttributeMaxDynamicSharedMemorySize, VQ_SMEM_B);

    prep_kernel<<<172, 256>>>(masks, cb);
    qkv_tc_kernel<<<dim3(Nn/128, 3), 256, QKV_SMEM_B>>>(ids, masks, emb,
                                                        Wq, bq, Wk, bk, Wv, bv);
    attn_tc_kernel<<<ATTN_GRID, 256, ATTN_SMEM_B>>>();
    combine_kernel<<<Nn/32, 256>>>();
    vq_tc_kernel<<<dim3(Nn/128, VQS), 256, VQ_SMEM_B>>>();
    final_kernel<<<Bb, 256>>>(cb, W_enc, b_enc, out);
}

// round 14
// speedup vs baseline: 1.0116x; 1.0116x over previous
#include <cuda_runtime.h>
#include <cuda_bf16.h>
#include <cstdint>
#include <math.h>

// ============================ problem constants ============================
namespace {
constexpr int Bb=128, Ll=50, Nn=Bb*Ll, Dd=64, Kc=1024;
constexpr int LDK = 72;           // bf16 smem row stride
constexpr int VQS = 4;            // VQ codebook splits
constexpr int NRB = Nn/128;       // 50 row blocks

// attn smem (bf16 elements)
constexpr int KS_OFF = 128*LDK;
constexpr int VS_OFF = KS_OFF + 2*128*LDK;
constexpr int SM_ELEMS = VS_OFF + 2*128*LDK;
constexpr int RS_OFF_B = SM_ELEMS*2;
constexpr int ATTN_SMEM_B = RS_OFF_B + 1024;   // 93184 B

// vq smem
constexpr int VQ_C_OFF  = 2*128*LDK;
constexpr int VQ_CN_B   = (VQ_C_OFF + 2*128*LDK)*2;
constexpr int VQ_RED_B  = VQ_CN_B + 256*4;
constexpr int VQ_SMEM_B = VQ_RED_B + 2*128*4*2;  // ~77KB (2 CTAs/SM fit)

// qkv smem (bf16 elements): H0h,H0l [128][LDK], Wh,Wl [64][LDK]
constexpr int QKV_H0L  = 128*LDK;
constexpr int QKV_WH   = 2*128*LDK;
constexpr int QKV_WL   = QKV_WH + 64*LDK;
constexpr int QKV_SMEM_B = (QKV_WL + 64*LDK)*2;   // 55296 B
}

// ============================ scratch (device globals) =====================
__device__ float g_h [Nn*Dd];
__device__ float g_acc[Nn*Dd];     // attention numerator (atomic accumulated)
__device__ float g_rsum[Nn];       // sum of u (atomic accumulated)
__device__ float g_denom[Bb];
__device__ float g_cnorm[Kc];
__device__ float g_vcolsum[Dd];    // atomic accumulated
__device__ float g_bval[VQS][Nn];
__device__ int   g_bidx[VQS][Nn];
__device__ __nv_bfloat16 g_qh[Nn*Dd];
__device__ __nv_bfloat16 g_kh[Nn*Dd];
__device__ __nv_bfloat16 g_vh[Nn*Dd];
__device__ __nv_bfloat16 g_cbh[Kc*Dd];
__device__ __nv_bfloat16 g_cbl[Kc*Dd];

// ============================ asm helpers ==================================
__device__ __forceinline__ uint32_t smaddr(const void* p) {
    return (uint32_t)__cvta_generic_to_shared(p);
}
__device__ __forceinline__ void ldsm_x4(uint32_t a, uint32_t& r0, uint32_t& r1,
                                        uint32_t& r2, uint32_t& r3) {
    asm volatile("ldmatrix.sync.aligned.m8n8.x4.shared.b16 {%0,%1,%2,%3},[%4];"
                 : "=r"(r0), "=r"(r1), "=r"(r2), "=r"(r3) : "r"(a));
}
__device__ __forceinline__ void ldsm_x4t(uint32_t a, uint32_t& r0, uint32_t& r1,
                                         uint32_t& r2, uint32_t& r3) {
    asm volatile("ldmatrix.sync.aligned.m8n8.x4.trans.shared.b16 {%0,%1,%2,%3},[%4];"
                 : "=r"(r0), "=r"(r1), "=r"(r2), "=r"(r3) : "r"(a));
}
__device__ __forceinline__ void mma16816(float c[4], const uint32_t a[4],
                                         const uint32_t b0, const uint32_t b1) {
    asm volatile("mma.sync.aligned.m16n8k16.row.col.f32.bf16.bf16.f32 "
                 "{%0,%1,%2,%3},{%4,%5,%6,%7},{%8,%9},{%0,%1,%2,%3};"
                 : "+f"(c[0]), "+f"(c[1]), "+f"(c[2]), "+f"(c[3])
                 : "r"(a[0]), "r"(a[1]), "r"(a[2]), "r"(a[3]), "r"(b0), "r"(b1));
}
__device__ __forceinline__ void cpa16(uint32_t dst, const void* src) {
    asm volatile("cp.async.cg.shared.global [%0],[%1],16;" :: "r"(dst), "l"(src));
}
__device__ __forceinline__ uint32_t packbf2(float lo, float hi) {
    __nv_bfloat162 v = __float22bfloat162_rn(make_float2(lo, hi));
    return *(uint32_t*)&v;
}

// ---------------------------------------------------------------------------
// 1. fused embed + tensor-core QKV (y=0..2) and prep plane (y=3):
//    codebook hi/lo split + cnorm + denom (zeroing handled by memsets)
// ---------------------------------------------------------------------------
__global__ void __launch_bounds__(256) qkv_tc_kernel(
    const int* __restrict__ ids, const int* __restrict__ masks,
    const float* __restrict__ emb, const float* __restrict__ cb,
    const float* __restrict__ Wq, const float* __restrict__ bq,
    const float* __restrict__ Wk, const float* __restrict__ bk,
    const float* __restrict__ Wv, const float* __restrict__ bv)
{
    extern __shared__ __nv_bfloat16 qsm[];
    const int tid = threadIdx.x, lane = tid & 31, wid = tid >> 5;
    const int wm = wid >> 1, wn = wid & 1;
    const int q0 = blockIdx.x * 128;
    const int m  = blockIdx.y;

    if (m == 3) {   // ---- prep plane (50 CTAs) ----
        const int cta = blockIdx.x;
        for (int i = cta*256 + tid; i < Kc*Dd/4; i += NRB*256) {
            float4 c = ((const float4*)cb)[i];
            float cv[4] = {c.x, c.y, c.z, c.w};
            #pragma unroll
            for (int j = 0; j < 4; j++) {
                __nv_bfloat16 h = __float2bfloat16(cv[j]);
                g_cbh[i*4 + j] = h;
                g_cbl[i*4 + j] = __float2bfloat16(cv[j] - __bfloat162float(h));
            }
        }
        int k = cta*256 + tid;
        if (k < Kc) {
            float s = 0.0f;
            #pragma unroll 4
            for (int d4 = 0; d4 < 16; d4++) {
                float4 c = ((const float4*)cb)[k*16 + d4];
                s = fmaf(c.x,c.x, fmaf(c.y,c.y, fmaf(c.z,c.z, fmaf(c.w,c.w, s))));
            }
            g_cnorm[k] = s;
        }
        if (cta == 4 && tid < Bb) {
            float s = 0.0f;
            for (int l = 0; l < Ll; l++) s += (masks[tid*Ll + l] >= 1) ? 1.0f : 0.0f;
            g_denom[tid] = s;
        }
        return;
    }

    __nv_bfloat16* H0h = qsm;
    __nv_bfloat16* H0l = qsm + QKV_H0L;
    __nv_bfloat16* Wh  = qsm + QKV_WH;
    __nv_bfloat16* Wl  = qsm + QKV_WL;

    const float* Wsel = (m == 0) ? Wq : (m == 1) ? Wk : Wv;
    const float* bsel = (m == 0) ? bq : (m == 1) ? bk : bv;
    __nv_bfloat16* osel = (m == 0) ? g_qh : (m == 1) ? g_kh : g_vh;

    // embed gather + mask + hi/lo split, straight into smem
    {
        int r = tid >> 1, half = tid & 1;
        int n = q0 + r;
        float mval = (masks[n] >= 1) ? 1.0f : 0.0f;
        const float4* src = (const float4*)(emb + (size_t)ids[n] * Dd) + half*8;
        #pragma unroll
        for (int j = 0; j < 8; j++) {
            float4 v = src[j];
            float vv[4] = {v.x*mval, v.y*mval, v.z*mval, v.w*mval};
            float hi[4], lo[4];
            #pragma unroll
            for (int e = 0; e < 4; e++) {
                __nv_bfloat16 h = __float2bfloat16(vv[e]);
                hi[e] = __bfloat162float(h);
                lo[e] = vv[e] - hi[e];
            }
            int col = half*32 + j*4;
            *(uint32_t*)&H0h[r*LDK + col]     = packbf2(hi[0], hi[1]);
            *(uint32_t*)&H0h[r*LDK + col + 2] = packbf2(hi[2], hi[3]);
            *(uint32_t*)&H0l[r*LDK + col]     = packbf2(lo[0], lo[1]);
            *(uint32_t*)&H0l[r*LDK + col + 2] = packbf2(lo[2], lo[3]);
        }
    }
    // weight load (no sync needed yet; W region disjoint from H0)
    for (int idx = tid; idx < 4096; idx += 256) {
        int k = idx >> 6, n = idx & 63;
        float w = Wsel[idx];
        __nv_bfloat16 h = __float2bfloat16(w);
        Wh[k*LDK + n] = h;
        Wl[k*LDK + n] = __float2bfloat16(w - __bfloat162float(h));
    }
    __syncthreads();

    uint32_t ah[2][4][4], al[2][4][4];
    #pragma unroll
    for (int mi = 0; mi < 2; mi++)
        #pragma unroll
        for (int ks = 0; ks < 4; ks++) {
            int row = wm*32 + mi*16 + (lane & 15);
            ldsm_x4(smaddr(H0h + row*LDK + ks*16 + (lane >> 4)*8),
                    ah[mi][ks][0], ah[mi][ks][1], ah[mi][ks][2], ah[mi][ks][3]);
            ldsm_x4(smaddr(H0l + row*LDK + ks*16 + (lane >> 4)*8),
                    al[mi][ks][0], al[mi][ks][1], al[mi][ks][2], al[mi][ks][3]);
        }

    float c[2][4][4] = {};
    #pragma unroll
    for (int ks = 0; ks < 4; ks++) {
        int kr = ks*16 + (lane & 15);
        #pragma unroll
        for (int njp = 0; njp < 2; njp++) {
            uint32_t bh[4], bl[4];
            uint32_t colg = (wn*4 + njp*2 + (lane >> 4))*8;
            ldsm_x4t(smaddr(Wh + kr*LDK + colg), bh[0], bh[1], bh[2], bh[3]);
            ldsm_x4t(smaddr(Wl + kr*LDK + colg), bl[0], bl[1], bl[2], bl[3]);
            #pragma unroll
            for (int mi = 0; mi < 2; mi++) {
                mma16816(c[mi][njp*2],   ah[mi][ks], bh[0], bh[1]);
                mma16816(c[mi][njp*2],   al[mi][ks], bh[0], bh[1]);
                mma16816(c[mi][njp*2],   ah[mi][ks], bl[0], bl[1]);
                mma16816(c[mi][njp*2+1], ah[mi][ks], bh[2], bh[3]);
                mma16816(c[mi][njp*2+1], al[mi][ks], bh[2], bh[3]);
                mma16816(c[mi][njp*2+1], ah[mi][ks], bl[2], bl[3]);
            }
        }
    }

    float csum[4][2];
    #pragma unroll
    for (int nj = 0; nj < 4; nj++) { csum[nj][0] = 0.0f; csum[nj][1] = 0.0f; }

    #pragma unroll
    for (int mi = 0; mi < 2; mi++)
        #pragma unroll
        for (int nj = 0; nj < 4; nj++) {
            int col0 = wn*32 + nj*8 + (lane & 3)*2;
            float b0 = bsel[col0], b1 = bsel[col0 + 1];
            float c0 = c[mi][nj][0] + b0, c1 = c[mi][nj][1] + b1;
            float c2 = c[mi][nj][2] + b0, c3 = c[mi][nj][3] + b1;
            int r0 = q0 + wm*32 + mi*16 + (lane >> 2);
            *(uint32_t*)&osel[r0*64 + col0]       = packbf2(c0, c1);
            *(uint32_t*)&osel[(r0 + 8)*64 + col0] = packbf2(c2, c3);
            if (m == 2) { csum[nj][0] += c0 + c2; csum[nj][1] += c1 + c3; }
        }

    if (m == 2) {
        #pragma unroll
        for (int nj = 0; nj < 4; nj++) {
            #pragma unroll
            for (int off = 4; off <= 16; off <<= 1) {
                csum[nj][0] += __shfl_xor_sync(0xffffffffu, csum[nj][0], off);
                csum[nj][1] += __shfl_xor_sync(0xffffffffu, csum[nj][1], off);
            }
            if (lane < 4) {
                int col = wn*32 + nj*8 + lane*2;
                atomicAdd(&g_vcolsum[col],     csum[nj][0]);
                atomicAdd(&g_vcolsum[col + 1], csum[nj][1]);
            }
        }
    }
}

// ---------------------------------------------------------------------------
// 2. tensor-core attention partials (expm1 form), SPL=6 (9/9/8/8/8/8 tiles),
//    atomic accumulation into g_acc / g_rsum
// ---------------------------------------------------------------------------
__global__ void __launch_bounds__(256) attn_tc_kernel() {
    extern __shared__ __nv_bfloat16 sm[];
    __nv_bfloat16* Qs = sm;
    __nv_bfloat16* Ks[2] = { sm + KS_OFF, sm + KS_OFF + 128*LDK };
    __nv_bfloat16* Vs[2] = { sm + VS_OFF, sm + VS_OFF + 128*LDK };
    float* rsred = (float*)((char*)sm + RS_OFF_B);

    const int tid = threadIdx.x, lane = tid & 31, wid = tid >> 5;
    const int wm = wid >> 1, wn = wid & 1;
    const int q0 = blockIdx.x * 128;
    const int s  = blockIdx.y;
    const int base_t = s*8 + (s < 2 ? s : 2);
    const int tps    = 8 + (s < 2 ? 1 : 0);
    const int kvbase = base_t * 128;

    for (int c = tid; c < 1024; c += 256) {
        int r = c >> 3, g = c & 7;
        cpa16(smaddr(Qs + r*LDK + g*8), g_qh + (q0 + r)*64 + g*8);
        cpa16(smaddr(Ks[0] + r*LDK + g*8), g_kh + (kvbase + r)*64 + g*8);
        cpa16(smaddr(Vs[0] + r*LDK + g*8), g_vh + (kvbase + r)*64 + g*8);
    }
    asm volatile("cp.async.commit_group;");
    asm volatile("cp.async.wait_group 0;");
    __syncthreads();

    uint32_t qa[2][4][4];
    #pragma unroll
    for (int mi = 0; mi < 2; mi++)
        #pragma unroll
        for (int ks = 0; ks < 4; ks++) {
            int row = wm*32 + mi*16 + (lane & 15);
            ldsm_x4(smaddr(Qs + row*LDK + ks*16 + (lane >> 4)*8),
                    qa[mi][ks][0], qa[mi][ks][1], qa[mi][ks][2], qa[mi][ks][3]);
        }

    float o[2][8][4] = {};
    float rs[2][2]   = {};

    for (int t = 0; t < tps; t++) {
        const int buf = t & 1;
        if (t + 1 < tps) {
            const int kv1 = kvbase + (t+1)*128;
            __nv_bfloat16* Kd = Ks[buf^1];
            __nv_bfloat16* Vd = Vs[buf^1];
            for (int c = tid; c < 1024; c += 256) {
                int r = c >> 3, g = c & 7;
                cpa16(smaddr(Kd + r*LDK + g*8), g_kh + (kv1 + r)*64 + g*8);
                cpa16(smaddr(Vd + r*LDK + g*8), g_vh + (kv1 + r)*64 + g*8);
            }
        }
        asm volatile("cp.async.commit_group;");
        asm volatile("cp.async.wait_group 1;");
        __syncthreads();

        float c[2][8][4] = {};
        const __nv_bfloat16* Kb = Ks[buf];
        #pragma unroll
        for (int nj = 0; nj < 8; nj++) {
            uint32_t kb[4][2];
            int r = wn*64 + nj*8 + (lane & 7);
            ldsm_x4(smaddr(Kb + r*LDK + (lane >> 3)*8),
                    kb[0][0], kb[0][1], kb[1][0], kb[1][1]);
            ldsm_x4(smaddr(Kb + r*LDK + 32 + (lane >> 3)*8),
                    kb[2][0], kb[2][1], kb[3][0], kb[3][1]);
            #pragma unroll
            for (int mi = 0; mi < 2; mi++)
                #pragma unroll
                for (int ks = 0; ks < 4; ks++)
                    mma16816(c[mi][nj], qa[mi][ks], kb[ks][0], kb[ks][1]);
        }

        #pragma unroll
        for (int mi = 0; mi < 2; mi++)
            #pragma unroll
            for (int nj = 0; nj < 8; nj++)
                #pragma unroll
                for (int e = 0; e < 4; e++) {
                    float x = c[mi][nj][e] * 0.125f;
                    float u = x * (1.0f + x * (0.5f + x * 0.16666667f));
                    c[mi][nj][e] = u;
                    rs[mi][e >> 1] += u;
                }

        const __nv_bfloat16* Vb = Vs[buf];
        #pragma unroll
        for (int ss = 0; ss < 4; ss++) {
            uint32_t a[2][4];
            #pragma unroll
            for (int mi = 0; mi < 2; mi++) {
                const float* u0 = c[mi][2*ss];
                const float* u1 = c[mi][2*ss + 1];
                a[mi][0] = packbf2(u0[0], u0[1]);
                a[mi][1] = packbf2(u0[2], u0[3]);
                a[mi][2] = packbf2(u1[0], u1[1]);
                a[mi][3] = packbf2(u1[2], u1[3]);
            }
            int kr = wn*64 + ss*16 + (lane & 15);
            #pragma unroll
            for (int jd = 0; jd < 8; jd += 2) {
                uint32_t b[4];
                ldsm_x4t(smaddr(Vb + kr*LDK + (jd + (lane >> 4))*8),
                         b[0], b[1], b[2], b[3]);
                #pragma unroll
                for (int mi = 0; mi < 2; mi++) {
                    mma16816(o[mi][jd],     a[mi], b[0], b[1]);
                    mma16816(o[mi][jd + 1], a[mi], b[2], b[3]);
                }
            }
        }
        __syncthreads();
    }

    #pragma unroll
    for (int mi = 0; mi < 2; mi++)
        #pragma unroll
        for (int h = 0; h < 2; h++) {
            float v = rs[mi][h];
            v += __shfl_xor_sync(0xffffffffu, v, 1);
            v += __shfl_xor_sync(0xffffffffu, v, 2);
            if ((lane & 3) == 0) {
                int row = wm*32 + mi*16 + h*8 + (lane >> 2);
                rsred[wn*128 + row] = v;
            }
        }

    float* Ored = (float*)sm;  // [128][66] floats
    if (wn == 1) {
        #pragma unroll
        for (int mi = 0; mi < 2; mi++)
            #pragma unroll
            for (int jd = 0; jd < 8; jd++) {
                int r0 = wm*32 + mi*16 + (lane >> 2);
                int col = jd*8 + (lane & 3)*2;
                float* p = Ored + r0*66 + col;
                p[0] = o[mi][jd][0]; p[1] = o[mi][jd][1];
                p = Ored + (r0 + 8)*66 + col;
                p[0] = o[mi][jd][2]; p[1] = o[mi][jd][3];
            }
    }
    __syncthreads();
    if (tid < 128)
        atomicAdd(&g_rsum[q0 + tid], rsred[tid] + rsred[128 + tid]);
    if (wn == 0) {
        #pragma unroll
        for (int mi = 0; mi < 2; mi++)
            #pragma unroll
            for (int jd = 0; jd < 8; jd++) {
                int r0 = wm*32 + mi*16 + (lane >> 2);
                int col = jd*8 + (lane & 3)*2;
                float2 p0 = *(float2*)(Ored + r0*66 + col);
                float2 p1 = *(float2*)(Ored + (r0 + 8)*66 + col);
                atomicAdd(&g_acc[(q0 + r0)*64 + col],     o[mi][jd][0] + p0.x);
                atomicAdd(&g_acc[(q0 + r0)*64 + col + 1], o[mi][jd][1] + p0.y);
                atomicAdd(&g_acc[(q0 + r0 + 8)*64 + col],     o[mi][jd][2] + p1.x);
                atomicAdd(&g_acc[(q0 + r0 + 8)*64 + col + 1], o[mi][jd][3] + p1.y);
            }
    }
}

// ---------------------------------------------------------------------------
// 3. fused combine + tensor-core VQ argmin (4-way codebook split, 2 CTAs/SM)
// ---------------------------------------------------------------------------
__global__ void __launch_bounds__(256, 2) vq_tc_kernel() {
    extern __shared__ __nv_bfloat16 vsm[];
    __nv_bfloat16* Fh = vsm;
    __nv_bfloat16* Fl = vsm + 128*LDK;
    __nv_bfloat16* Ch = vsm + VQ_C_OFF;
    __nv_bfloat16* Cl = vsm + VQ_C_OFF + 128*LDK;
    float* cns  = (float*)((char*)vsm + VQ_CN_B);    // 256 floats
    float* redv = (float*)((char*)vsm + VQ_RED_B);   // 256 floats (+ints after)
    int*   redi = (int*)(redv + 256);

    const int tid = threadIdx.x, lane = tid & 31, wid = tid >> 5;
    const int wm = wid >> 1, wn = wid & 1;
    const int q0 = blockIdx.x * 128;
    const int sy = blockIdx.y;
    const int kbase = sy * (Kc/VQS);     // 256 codes per split

    // --- fused combine: h = (vcolsum + acc) / (Nn + rsum), hi/lo into smem
    float* rs_s = redv;          // 128 floats (read early only)
    float* vcol = redv + 128;    // 64 floats
    if (tid < 128) rs_s[tid] = (float)Nn + g_rsum[q0 + tid];
    else if (tid < 192) vcol[tid - 128] = g_vcolsum[tid - 128];
    if (tid < 256) cns[tid] = g_cnorm[kbase + tid];
    __syncthreads();

    #pragma unroll
    for (int it = 0; it < 8; it++) {
        int i = it*256 + tid;          // float4 index in [0, 2048)
        int r = i >> 4, f = i & 15;
        float4 a = ((const float4*)g_acc)[(q0 + r)*16 + f];
        float4 vc = *(const float4*)&vcol[f*4];
        float inv = 1.0f / rs_s[r];
        float hv[4] = {(a.x+vc.x)*inv, (a.y+vc.y)*inv, (a.z+vc.z)*inv, (a.w+vc.w)*inv};
        if (sy == 0)
            ((float4*)g_h)[(q0 + r)*16 + f] = make_float4(hv[0], hv[1], hv[2], hv[3]);
        float hi[4], lo[4];
        #pragma unroll
        for (int e = 0; e < 4; e++) {
            __nv_bfloat16 h = __float2bfloat16(hv[e]);
            hi[e] = __bfloat162float(h);
            lo[e] = hv[e] - hi[e];
        }
        int col = f*4;
        *(uint32_t*)&Fh[r*LDK + col]     = packbf2(hi[0], hi[1]);
        *(uint32_t*)&Fh[r*LDK + col + 2] = packbf2(hi[2], hi[3]);
        *(uint32_t*)&Fl[r*LDK + col]     = packbf2(lo[0], lo[1]);
        *(uint32_t*)&Fl[r*LDK + col + 2] = packbf2(lo[2], lo[3]);
    }
    __syncthreads();

    uint32_t fha[2][4][4], fla[2][4][4];
    #pragma unroll
    for (int mi = 0; mi < 2; mi++)
        #pragma unroll
        for (int ks = 0; ks < 4; ks++) {
            int row = wm*32 + mi*16 + (lane & 15);
            ldsm_x4(smaddr(Fh + row*LDK + ks*16 + (lane >> 4)*8),
                    fha[mi][ks][0], fha[mi][ks][1], fha[mi][ks][2], fha[mi][ks][3]);
            ldsm_x4(smaddr(Fl + row*LDK + ks*16 + (lane >> 4)*8),
                    fla[mi][ks][0], fla[mi][ks][1], fla[mi][ks][2], fla[mi][ks][3]);
        }

    float best[2][2];
    int   bidx[2][2];
    #pragma unroll
    for (int mi = 0; mi < 2; mi++)
        #pragma unroll
        for (int h = 0; h < 2; h++) { best[mi][h] = 3.4e38f; bidx[mi][h] = 0; }

    for (int t = 0; t < Kc/VQS/128; t++) {   // 2 tiles
        __syncthreads();
        const int c0 = (kbase + t*128)*64;
        for (int c = tid; c < 1024; c += 256) {
            int r = c >> 3, g = c & 7;
            cpa16(smaddr(Ch + r*LDK + g*8), g_cbh + c0 + r*64 + g*8);
            cpa16(smaddr(Cl + r*LDK + g*8), g_cbl + c0 + r*64 + g*8);
        }
        asm volatile("cp.async.commit_group;");
        asm volatile("cp.async.wait_group 0;");
        __syncthreads();

        float c[2][8][4] = {};
        #pragma unroll
        for (int nj = 0; nj < 8; nj++) {
            uint32_t chb[4][2], clb[4][2];
            int r = wn*64 + nj*8 + (lane & 7);
            ldsm_x4(smaddr(Ch + r*LDK + (lane >> 3)*8),
                    chb[0][0], chb[0][1], chb[1][0], chb[1][1]);
            ldsm_x4(smaddr(Ch + r*LDK + 32 + (lane >> 3)*8),
                    chb[2][0], chb[2][1], chb[3][0], chb[3][1]);
            ldsm_x4(smaddr(Cl + r*LDK + (lane >> 3)*8),
                    clb[0][0], clb[0][1], clb[1][0], clb[1][1]);
            ldsm_x4(smaddr(Cl + r*LDK + 32 + (lane >> 3)*8),
                    clb[2][0], clb[2][1], clb[3][0], clb[3][1]);
            #pragma unroll
            for (int mi = 0; mi < 2; mi++)
                #pragma unroll
                for (int ks = 0; ks < 4; ks++) {
                    mma16816(c[mi][nj], fha[mi][ks], chb[ks][0], chb[ks][1]);
                    mma16816(c[mi][nj], fla[mi][ks], chb[ks][0], chb[ks][1]);
                    mma16816(c[mi][nj], fha[mi][ks], clb[ks][0], clb[ks][1]);
                }
        }

        // ascending col order per thread -> '<' keeps first (lowest) index
        #pragma unroll
        for (int mi = 0; mi < 2; mi++)
            #pragma unroll
            for (int nj = 0; nj < 8; nj++)
                #pragma unroll
                for (int e = 0; e < 4; e++) {
                    int lcol = t*128 + wn*64 + nj*8 + (lane & 3)*2 + (e & 1);
                    float d2 = cns[lcol] - 2.0f * c[mi][nj][e];
                    int h = e >> 1;
                    if (d2 < best[mi][h]) { best[mi][h] = d2; bidx[mi][h] = kbase + lcol; }
                }
    }

    #pragma unroll
    for (int mi = 0; mi < 2; mi++)
        #pragma unroll
        for (int h = 0; h < 2; h++) {
            float v = best[mi][h]; int ix = bidx[mi][h];
            #pragma unroll
            for (int off = 1; off <= 2; off <<= 1) {
                float v2 = __shfl_xor_sync(0xffffffffu, v, off);
                int   i2 = __shfl_xor_sync(0xffffffffu, ix, off);
                if (v2 < v || (v2 == v && i2 < ix)) { v = v2; ix = i2; }
            }
            if ((lane & 3) == 0) {
                int row = wm*32 + mi*16 + h*8 + (lane >> 2);
                redv[wn*128 + row] = v;
                redi[wn*128 + row] = ix;
            }
        }
    __syncthreads();
    if (tid < 128) {
        float v0 = redv[tid], v1 = redv[128 + tid];
        int   i0 = redi[tid], i1 = redi[128 + tid];
        bool take1 = (v1 < v0) || (v1 == v0 && i1 < i0);
        g_bval[sy][q0 + tid] = take1 ? v1 : v0;
        g_bidx[sy][q0 + tid] = take1 ? i1 : i0;
    }
}

// ---------------------------------------------------------------------------
// 4. merge VQ splits + per-batch means + final projection
//    (256 threads: 4 l-groups x 64 dims, smem reduce)
// ---------------------------------------------------------------------------
__global__ void __launch_bounds__(256) final_kernel(
    const float* __restrict__ cb, const float* __restrict__ W_enc,
    const float* __restrict__ b_enc, float* __restrict__ out)
{
    const int b = blockIdx.x, tid = threadIdx.x;
    const int d = tid & 63, grp = tid >> 6;    // 4 groups of 64
    __shared__ float sv[4*64], sh2[4*64], x[2*Dd];

    float vs = 0.0f, hs = 0.0f;
    for (int l = grp; l < Ll; l += 4) {
        int n = b*Ll + l;
        // splits have strictly increasing index ranges; strict '<' scan in
        // split order keeps the overall first-index minimum
        float bv = g_bval[0][n]; int bi = g_bidx[0][n];
        #pragma unroll
        for (int sp = 1; sp < VQS; sp++) {
            float v = g_bval[sp][n];
            if (v < bv) { bv = v; bi = g_bidx[sp][n]; }
        }
        vs += cb[(size_t)bi*Dd + d];
        hs += g_h[n*Dd + d];
    }
    sv[grp*64 + d] = vs;
    sh2[grp*64 + d] = hs;
    __syncthreads();
    if (tid < 64) {
        float den = g_denom[b];
        float v  = sv[tid] + sv[64 + tid] + sv[128 + tid] + sv[192 + tid];
        float hh = sh2[tid] + sh2[64 + tid] + sh2[128 + tid] + sh2[192 + tid];
        x[tid]      = v / den;
        x[Dd + tid] = hh / (den + 1e-9f);
    }
    __syncthreads();
    if (tid < 64) {
        float a0 = b_enc[d], a1 = 0.f, a2 = 0.f, a3 = 0.f;
        #pragma unroll 8
        for (int i = 0; i < 2*Dd; i += 4) {
            a0 = fmaf(x[i],     W_enc[i*Dd + d],       a0);
            a1 = fmaf(x[i + 1], W_enc[(i + 1)*Dd + d], a1);
            a2 = fmaf(x[i + 2], W_enc[(i + 2)*Dd + d], a2);
            a3 = fmaf(x[i + 3], W_enc[(i + 3)*Dd + d], a3);
        }
        out[b*Dd + d] = (a0 + a1) + (a2 + a3);
    }
}

// ---------------------------------------------------------------------------
extern "C" void kernel_launch(void* const* d_in, const int* in_sizes, int n_in,
                              void* d_out, int out_size) {
    const int*   ids   = (const int*)d_in[0];
    const int*   masks = (const int*)d_in[1];
    const float* emb   = (const float*)d_in[2];
    const float* cb    = (const float*)d_in[3];
    const float* Wq    = (const float*)d_in[4];
    const float* bq    = (const float*)d_in[5];
    const float* Wk    = (const float*)d_in[6];
    const float* bk    = (const float*)d_in[7];
    const float* Wv    = (const float*)d_in[8];
    const float* bv    = (const float*)d_in[9];
    const float* W_enc = (const float*)d_in[10];
    const float* b_enc = (const float*)d_in[11];
    float* out = (float*)d_out;

    cudaFuncSetAttribute((const void*)qkv_tc_kernel,
                         cudaFuncAttributeMaxDynamicSharedMemorySize, QKV_SMEM_B);
    cudaFuncSetAttribute((const void*)attn_tc_kernel,
                         cudaFuncAttributeMaxDynamicSharedMemorySize, ATTN_SMEM_B);
    cudaFuncSetAttribute((const void*)vq_tc_kernel,
                         cudaFuncAttributeMaxDynamicSharedMemorySize, VQ_SMEM_B);

    // zero the atomic accumulators via memset nodes (graph-capturable)
    void *p_acc, *p_rsum, *p_vcs;
    cudaGetSymbolAddress(&p_acc,  g_acc);
    cudaGetSymbolAddress(&p_rsum, g_rsum);
    cudaGetSymbolAddress(&p_vcs,  g_vcolsum);
    cudaMemsetAsync(p_acc,  0, sizeof(float)*Nn*Dd);
    cudaMemsetAsync(p_rsum, 0, sizeof(float)*Nn);
    cudaMemsetAsync(p_vcs,  0, sizeof(float)*Dd);

    qkv_tc_kernel<<<dim3(NRB, 4), 256, QKV_SMEM_B>>>(ids, masks, emb, cb,
                                                     Wq, bq, Wk, bk, Wv, bv);
    attn_tc_kernel<<<dim3(NRB, 6), 256, ATTN_SMEM_B>>>();
    vq_tc_kernel<<<dim3(NRB, VQS), 256, VQ_SMEM_B>>>();
    final_kernel<<<Bb, 256>>>(cb, W_enc, b_enc, out);
}

// round 15
// speedup vs baseline: 1.1716x; 1.1581x over previous
#include <cuda_runtime.h>
#include <cuda_bf16.h>
#include <cstdint>
#include <math.h>

// ============================ problem constants ============================
namespace {
constexpr int Bb=128, Ll=50, Nn=Bb*Ll, Dd=64, Kc=1024;
constexpr int LDK = 72;           // bf16 smem row stride
constexpr int VQS = 4;            // VQ codebook splits

// attn smem (bf16 elements)
constexpr int KS_OFF = 128*LDK;
constexpr int VS_OFF = KS_OFF + 2*128*LDK;
constexpr int SM_ELEMS = VS_OFF + 2*128*LDK;
constexpr int RS_OFF_B = SM_ELEMS*2;
constexpr int ATTN_SMEM_B = RS_OFF_B + 1024;   // 93184 B

// vq smem
constexpr int VQ_C_OFF  = 2*128*LDK;
constexpr int VQ_CN_B   = (VQ_C_OFF + 2*128*LDK)*2;
constexpr int VQ_RED_B  = VQ_CN_B + 256*4;
constexpr int VQ_SMEM_B = VQ_RED_B + 2*128*4*2;  // ~77KB (2 CTAs/SM fit)

// qkv smem (bf16 elements): H0h,H0l [128][LDK], Wh,Wl [64][LDK]
constexpr int QKV_H0L  = 128*LDK;
constexpr int QKV_WH   = 2*128*LDK;
constexpr int QKV_WL   = QKV_WH + 64*LDK;
constexpr int QKV_SMEM_B = (QKV_WL + 64*LDK)*2;   // 55296 B
}

// ============================ scratch (device globals) =====================
__device__ float g_h [Nn*Dd];
__device__ float g_acc[Nn*Dd];     // attention numerator (atomic accumulated)
__device__ float g_rsum[Nn];       // sum of u (atomic accumulated)
__device__ float g_denom[Bb];
__device__ float g_cnorm[Kc];
__device__ float g_vcolsum[Dd];    // atomic accumulated
__device__ float g_bval[VQS][Nn];
__device__ int   g_bidx[VQS][Nn];
__device__ __nv_bfloat16 g_qh[Nn*Dd];
__device__ __nv_bfloat16 g_kh[Nn*Dd];
__device__ __nv_bfloat16 g_vh[Nn*Dd];
__device__ __nv_bfloat16 g_cbh[Kc*Dd];
__device__ __nv_bfloat16 g_cbl[Kc*Dd];

// ============================ asm helpers ==================================
__device__ __forceinline__ uint32_t smaddr(const void* p) {
    return (uint32_t)__cvta_generic_to_shared(p);
}
__device__ __forceinline__ void ldsm_x4(uint32_t a, uint32_t& r0, uint32_t& r1,
                                        uint32_t& r2, uint32_t& r3) {
    asm volatile("ldmatrix.sync.aligned.m8n8.x4.shared.b16 {%0,%1,%2,%3},[%4];"
                 : "=r"(r0), "=r"(r1), "=r"(r2), "=r"(r3) : "r"(a));
}
__device__ __forceinline__ void ldsm_x4t(uint32_t a, uint32_t& r0, uint32_t& r1,
                                         uint32_t& r2, uint32_t& r3) {
    asm volatile("ldmatrix.sync.aligned.m8n8.x4.trans.shared.b16 {%0,%1,%2,%3},[%4];"
                 : "=r"(r0), "=r"(r1), "=r"(r2), "=r"(r3) : "r"(a));
}
__device__ __forceinline__ void mma16816(float c[4], const uint32_t a[4],
                                         const uint32_t b0, const uint32_t b1) {
    asm volatile("mma.sync.aligned.m16n8k16.row.col.f32.bf16.bf16.f32 "
                 "{%0,%1,%2,%3},{%4,%5,%6,%7},{%8,%9},{%0,%1,%2,%3};"
                 : "+f"(c[0]), "+f"(c[1]), "+f"(c[2]), "+f"(c[3])
                 : "r"(a[0]), "r"(a[1]), "r"(a[2]), "r"(a[3]), "r"(b0), "r"(b1));
}
__device__ __forceinline__ void cpa16(uint32_t dst, const void* src) {
    asm volatile("cp.async.cg.shared.global [%0],[%1],16;" :: "r"(dst), "l"(src));
}
__device__ __forceinline__ uint32_t packbf2(float lo, float hi) {
    __nv_bfloat162 v = __float22bfloat162_rn(make_float2(lo, hi));
    return *(uint32_t*)&v;
}

// ---------------------------------------------------------------------------
// 1. prep: codebook hi/lo split + cnorm (blocks 0..63), denom + vcolsum zero
//    (block 64), zero g_acc (65..164), zero g_rsum (165..171)
// ---------------------------------------------------------------------------
__global__ void prep_kernel(const int* __restrict__ masks,
                            const float* __restrict__ cb) {
    const int b = blockIdx.x, tid = threadIdx.x;
    if (b < 64) {
        int i = b*256 + tid;              // float4 index into cb
        float4 c = ((const float4*)cb)[i];
        float cv[4] = {c.x, c.y, c.z, c.w};
        #pragma unroll
        for (int j = 0; j < 4; j++) {
            __nv_bfloat16 h = __float2bfloat16(cv[j]);
            g_cbh[i*4 + j] = h;
            g_cbl[i*4 + j] = __float2bfloat16(cv[j] - __bfloat162float(h));
        }
        float part = fmaf(c.x,c.x, fmaf(c.y,c.y, fmaf(c.z,c.z, c.w*c.w)));
        #pragma unroll
        for (int off = 1; off <= 8; off <<= 1)
            part += __shfl_xor_sync(0xffffffffu, part, off);
        if ((tid & 15) == 0) g_cnorm[i >> 4] = part;
    } else if (b == 64) {
        if (tid < Bb) {
            float s = 0.0f;
            for (int l = 0; l < Ll; l++) s += (masks[tid*Ll + l] >= 1) ? 1.0f : 0.0f;
            g_denom[tid] = s;
        } else if (tid < Bb + Dd) {
            g_vcolsum[tid - Bb] = 0.0f;
        }
    } else if (b < 165) {
        float4 z = make_float4(0.f, 0.f, 0.f, 0.f);
        #pragma unroll
        for (int j = 0; j < 4; j++)
            ((float4*)g_acc)[(b-65)*1024 + j*256 + tid] = z;
    } else {
        int f4 = (b-165)*256 + tid;
        if (f4 < Nn/4)
            ((float4*)g_rsum)[f4] = make_float4(0.f, 0.f, 0.f, 0.f);
    }
}

// ---------------------------------------------------------------------------
// 2. fused embed + tensor-core QKV; one weight matrix per blockIdx.y
// ---------------------------------------------------------------------------
__global__ void __launch_bounds__(256) qkv_tc_kernel(
    const int* __restrict__ ids, const int* __restrict__ masks,
    const float* __restrict__ emb,
    const float* __restrict__ Wq, const float* __restrict__ bq,
    const float* __restrict__ Wk, const float* __restrict__ bk,
    const float* __restrict__ Wv, const float* __restrict__ bv)
{
    extern __shared__ __nv_bfloat16 qsm[];
    __nv_bfloat16* H0h = qsm;
    __nv_bfloat16* H0l = qsm + QKV_H0L;
    __nv_bfloat16* Wh  = qsm + QKV_WH;
    __nv_bfloat16* Wl  = qsm + QKV_WL;

    const int tid = threadIdx.x, lane = tid & 31, wid = tid >> 5;
    const int wm = wid >> 1, wn = wid & 1;
    const int q0 = blockIdx.x * 128;
    const int m  = blockIdx.y;

    const float* Wsel = (m == 0) ? Wq : (m == 1) ? Wk : Wv;
    const float* bsel = (m == 0) ? bq : (m == 1) ? bk : bv;
    __nv_bfloat16* osel = (m == 0) ? g_qh : (m == 1) ? g_kh : g_vh;

    // embed gather + mask + hi/lo split, straight into smem
    {
        int r = tid >> 1, half = tid & 1;
        int n = q0 + r;
        float mval = (masks[n] >= 1) ? 1.0f : 0.0f;
        const float4* src = (const float4*)(emb + (size_t)ids[n] * Dd) + half*8;
        #pragma unroll
        for (int j = 0; j < 8; j++) {
            float4 v = src[j];
            float vv[4] = {v.x*mval, v.y*mval, v.z*mval, v.w*mval};
            float hi[4], lo[4];
            #pragma unroll
            for (int e = 0; e < 4; e++) {
                __nv_bfloat16 h = __float2bfloat16(vv[e]);
                hi[e] = __bfloat162float(h);
                lo[e] = vv[e] - hi[e];
            }
            int col = half*32 + j*4;
            *(uint32_t*)&H0h[r*LDK + col]     = packbf2(hi[0], hi[1]);
            *(uint32_t*)&H0h[r*LDK + col + 2] = packbf2(hi[2], hi[3]);
            *(uint32_t*)&H0l[r*LDK + col]     = packbf2(lo[0], lo[1]);
            *(uint32_t*)&H0l[r*LDK + col + 2] = packbf2(lo[2], lo[3]);
        }
    }
    // weight load (no sync needed yet; W region disjoint from H0)
    for (int idx = tid; idx < 4096; idx += 256) {
        int k = idx >> 6, n = idx & 63;
        float w = Wsel[idx];
        __nv_bfloat16 h = __float2bfloat16(w);
        Wh[k*LDK + n] = h;
        Wl[k*LDK + n] = __float2bfloat16(w - __bfloat162float(h));
    }
    __syncthreads();

    uint32_t ah[2][4][4], al[2][4][4];
    #pragma unroll
    for (int mi = 0; mi < 2; mi++)
        #pragma unroll
        for (int ks = 0; ks < 4; ks++) {
            int row = wm*32 + mi*16 + (lane & 15);
            ldsm_x4(smaddr(H0h + row*LDK + ks*16 + (lane >> 4)*8),
                    ah[mi][ks][0], ah[mi][ks][1], ah[mi][ks][2], ah[mi][ks][3]);
            ldsm_x4(smaddr(H0l + row*LDK + ks*16 + (lane >> 4)*8),
                    al[mi][ks][0], al[mi][ks][1], al[mi][ks][2], al[mi][ks][3]);
        }

    float c[2][4][4] = {};
    #pragma unroll
    for (int ks = 0; ks < 4; ks++) {
        int kr = ks*16 + (lane & 15);
        #pragma unroll
        for (int njp = 0; njp < 2; njp++) {
            uint32_t bh[4], bl[4];
            uint32_t colg = (wn*4 + njp*2 + (lane >> 4))*8;
            ldsm_x4t(smaddr(Wh + kr*LDK + colg), bh[0], bh[1], bh[2], bh[3]);
            ldsm_x4t(smaddr(Wl + kr*LDK + colg), bl[0], bl[1], bl[2], bl[3]);
            #pragma unroll
            for (int mi = 0; mi < 2; mi++) {
                mma16816(c[mi][njp*2],   ah[mi][ks], bh[0], bh[1]);
                mma16816(c[mi][njp*2],   al[mi][ks], bh[0], bh[1]);
                mma16816(c[mi][njp*2],   ah[mi][ks], bl[0], bl[1]);
                mma16816(c[mi][njp*2+1], ah[mi][ks], bh[2], bh[3]);
                mma16816(c[mi][njp*2+1], al[mi][ks], bh[2], bh[3]);
                mma16816(c[mi][njp*2+1], ah[mi][ks], bl[2], bl[3]);
            }
        }
    }

    float csum[4][2];
    #pragma unroll
    for (int nj = 0; nj < 4; nj++) { csum[nj][0] = 0.0f; csum[nj][1] = 0.0f; }

    #pragma unroll
    for (int mi = 0; mi < 2; mi++)
        #pragma unroll
        for (int nj = 0; nj < 4; nj++) {
            int col0 = wn*32 + nj*8 + (lane & 3)*2;
            float b0 = bsel[col0], b1 = bsel[col0 + 1];
            float c0 = c[mi][nj][0] + b0, c1 = c[mi][nj][1] + b1;
            float c2 = c[mi][nj][2] + b0, c3 = c[mi][nj][3] + b1;
            int r0 = q0 + wm*32 + mi*16 + (lane >> 2);
            *(uint32_t*)&osel[r0*64 + col0]       = packbf2(c0, c1);
            *(uint32_t*)&osel[(r0 + 8)*64 + col0] = packbf2(c2, c3);
            if (m == 2) { csum[nj][0] += c0 + c2; csum[nj][1] += c1 + c3; }
        }

    if (m == 2) {
        #pragma unroll
        for (int nj = 0; nj < 4; nj++) {
            #pragma unroll
            for (int off = 4; off <= 16; off <<= 1) {
                csum[nj][0] += __shfl_xor_sync(0xffffffffu, csum[nj][0], off);
                csum[nj][1] += __shfl_xor_sync(0xffffffffu, csum[nj][1], off);
            }
            if (lane < 4) {
                int col = wn*32 + nj*8 + lane*2;
                atomicAdd(&g_vcolsum[col],     csum[nj][0]);
                atomicAdd(&g_vcolsum[col + 1], csum[nj][1]);
            }
        }
    }
}

// ---------------------------------------------------------------------------
// 3. tensor-core attention partials (expm1 form), SPL=6 (9/9/8/8/8/8 tiles),
//    atomic accumulation into g_acc / g_rsum
// ---------------------------------------------------------------------------
__global__ void __launch_bounds__(256) attn_tc_kernel() {
    extern __shared__ __nv_bfloat16 sm[];
    __nv_bfloat16* Qs = sm;
    __nv_bfloat16* Ks[2] = { sm + KS_OFF, sm + KS_OFF + 128*LDK };
    __nv_bfloat16* Vs[2] = { sm + VS_OFF, sm + VS_OFF + 128*LDK };
    float* rsred = (float*)((char*)sm + RS_OFF_B);

    const int tid = threadIdx.x, lane = tid & 31, wid = tid >> 5;
    const int wm = wid >> 1, wn = wid & 1;
    const int q0 = blockIdx.x * 128;
    const int s  = blockIdx.y;
    const int base_t = s*8 + (s < 2 ? s : 2);
    const int tps    = 8 + (s < 2 ? 1 : 0);
    const int kvbase = base_t * 128;

    for (int c = tid; c < 1024; c += 256) {
        int r = c >> 3, g = c & 7;
        cpa16(smaddr(Qs + r*LDK + g*8), g_qh + (q0 + r)*64 + g*8);
        cpa16(smaddr(Ks[0] + r*LDK + g*8), g_kh + (kvbase + r)*64 + g*8);
        cpa16(smaddr(Vs[0] + r*LDK + g*8), g_vh + (kvbase + r)*64 + g*8);
    }
    asm volatile("cp.async.commit_group;");
    asm volatile("cp.async.wait_group 0;");
    __syncthreads();

    uint32_t qa[2][4][4];
    #pragma unroll
    for (int mi = 0; mi < 2; mi++)
        #pragma unroll
        for (int ks = 0; ks < 4; ks++) {
            int row = wm*32 + mi*16 + (lane & 15);
            ldsm_x4(smaddr(Qs + row*LDK + ks*16 + (lane >> 4)*8),
                    qa[mi][ks][0], qa[mi][ks][1], qa[mi][ks][2], qa[mi][ks][3]);
        }

    float o[2][8][4] = {};
    float rs[2][2]   = {};

    for (int t = 0; t < tps; t++) {
        const int buf = t & 1;
        if (t + 1 < tps) {
            const int kv1 = kvbase + (t+1)*128;
            __nv_bfloat16* Kd = Ks[buf^1];
            __nv_bfloat16* Vd = Vs[buf^1];
            for (int c = tid; c < 1024; c += 256) {
                int r = c >> 3, g = c & 7;
                cpa16(smaddr(Kd + r*LDK + g*8), g_kh + (kv1 + r)*64 + g*8);
                cpa16(smaddr(Vd + r*LDK + g*8), g_vh + (kv1 + r)*64 + g*8);
            }
        }
        asm volatile("cp.async.commit_group;");
        asm volatile("cp.async.wait_group 1;");
        __syncthreads();

        float c[2][8][4] = {};
        const __nv_bfloat16* Kb = Ks[buf];
        #pragma unroll
        for (int nj = 0; nj < 8; nj++) {
            uint32_t kb[4][2];
            int r = wn*64 + nj*8 + (lane & 7);
            ldsm_x4(smaddr(Kb + r*LDK + (lane >> 3)*8),
                    kb[0][0], kb[0][1], kb[1][0], kb[1][1]);
            ldsm_x4(smaddr(Kb + r*LDK + 32 + (lane >> 3)*8),
                    kb[2][0], kb[2][1], kb[3][0], kb[3][1]);
            #pragma unroll
            for (int mi = 0; mi < 2; mi++)
                #pragma unroll
                for (int ks = 0; ks < 4; ks++)
                    mma16816(c[mi][nj], qa[mi][ks], kb[ks][0], kb[ks][1]);
        }

        #pragma unroll
        for (int mi = 0; mi < 2; mi++)
            #pragma unroll
            for (int nj = 0; nj < 8; nj++)
                #pragma unroll
                for (int e = 0; e < 4; e++) {
                    float x = c[mi][nj][e] * 0.125f;
                    float u = x * (1.0f + x * (0.5f + x * 0.16666667f));
                    c[mi][nj][e] = u;
                    rs[mi][e >> 1] += u;
                }

        const __nv_bfloat16* Vb = Vs[buf];
        #pragma unroll
        for (int ss = 0; ss < 4; ss++) {
            uint32_t a[2][4];
            #pragma unroll
            for (int mi = 0; mi < 2; mi++) {
                const float* u0 = c[mi][2*ss];
                const float* u1 = c[mi][2*ss + 1];
                a[mi][0] = packbf2(u0[0], u0[1]);
                a[mi][1] = packbf2(u0[2], u0[3]);
                a[mi][2] = packbf2(u1[0], u1[1]);
                a[mi][3] = packbf2(u1[2], u1[3]);
            }
            int kr = wn*64 + ss*16 + (lane & 15);
            #pragma unroll
            for (int jd = 0; jd < 8; jd += 2) {
                uint32_t b[4];
                ldsm_x4t(smaddr(Vb + kr*LDK + (jd + (lane >> 4))*8),
                         b[0], b[1], b[2], b[3]);
                #pragma unroll
                for (int mi = 0; mi < 2; mi++) {
                    mma16816(o[mi][jd],     a[mi], b[0], b[1]);
                    mma16816(o[mi][jd + 1], a[mi], b[2], b[3]);
                }
            }
        }
        __syncthreads();
    }

    #pragma unroll
    for (int mi = 0; mi < 2; mi++)
        #pragma unroll
        for (int h = 0; h < 2; h++) {
            float v = rs[mi][h];
            v += __shfl_xor_sync(0xffffffffu, v, 1);
            v += __shfl_xor_sync(0xffffffffu, v, 2);
            if ((lane & 3) == 0) {
                int row = wm*32 + mi*16 + h*8 + (lane >> 2);
                rsred[wn*128 + row] = v;
            }
        }

    float* Ored = (float*)sm;  // [128][66] floats
    if (wn == 1) {
        #pragma unroll
        for (int mi = 0; mi < 2; mi++)
            #pragma unroll
            for (int jd = 0; jd < 8; jd++) {
                int r0 = wm*32 + mi*16 + (lane >> 2);
                int col = jd*8 + (lane & 3)*2;
                float* p = Ored + r0*66 + col;
                p[0] = o[mi][jd][0]; p[1] = o[mi][jd][1];
                p = Ored + (r0 + 8)*66 + col;
                p[0] = o[mi][jd][2]; p[1] = o[mi][jd][3];
            }
    }
    __syncthreads();
    if (tid < 128)
        atomicAdd(&g_rsum[q0 + tid], rsred[tid] + rsred[128 + tid]);
    if (wn == 0) {
        #pragma unroll
        for (int mi = 0; mi < 2; mi++)
            #pragma unroll
            for (int jd = 0; jd < 8; jd++) {
                int r0 = wm*32 + mi*16 + (lane >> 2);
                int col = jd*8 + (lane & 3)*2;
                float2 p0 = *(float2*)(Ored + r0*66 + col);
                float2 p1 = *(float2*)(Ored + (r0 + 8)*66 + col);
                atomicAdd(&g_acc[(q0 + r0)*64 + col],     o[mi][jd][0] + p0.x);
                atomicAdd(&g_acc[(q0 + r0)*64 + col + 1], o[mi][jd][1] + p0.y);
                atomicAdd(&g_acc[(q0 + r0 + 8)*64 + col],     o[mi][jd][2] + p1.x);
                atomicAdd(&g_acc[(q0 + r0 + 8)*64 + col + 1], o[mi][jd][3] + p1.y);
            }
    }
}

// ---------------------------------------------------------------------------
// 4. fused combine + tensor-core VQ argmin (4-way codebook split, 2 CTAs/SM)
// ---------------------------------------------------------------------------
__global__ void __launch_bounds__(256, 2) vq_tc_kernel() {
    extern __shared__ __nv_bfloat16 vsm[];
    __nv_bfloat16* Fh = vsm;
    __nv_bfloat16* Fl = vsm + 128*LDK;
    __nv_bfloat16* Ch = vsm + VQ_C_OFF;
    __nv_bfloat16* Cl = vsm + VQ_C_OFF + 128*LDK;
    float* cns  = (float*)((char*)vsm + VQ_CN_B);    // 256 floats
    float* redv = (float*)((char*)vsm + VQ_RED_B);   // 256 floats (+ints after)
    int*   redi = (int*)(redv + 256);

    const int tid = threadIdx.x, lane = tid & 31, wid = tid >> 5;
    const int wm = wid >> 1, wn = wid & 1;
    const int q0 = blockIdx.x * 128;
    const int sy = blockIdx.y;
    const int kbase = sy * (Kc/VQS);     // 256 codes per split

    // --- fused combine: h = (vcolsum + acc) / (Nn + rsum), hi/lo into smem
    float* rs_s = redv;          // 128 floats (read early only)
    float* vcol = redv + 128;    // 64 floats
    if (tid < 128) rs_s[tid] = (float)Nn + g_rsum[q0 + tid];
    else if (tid < 192) vcol[tid - 128] = g_vcolsum[tid - 128];
    if (tid < 256) cns[tid] = g_cnorm[kbase + tid];
    __syncthreads();

    #pragma unroll
    for (int it = 0; it < 8; it++) {
        int i = it*256 + tid;          // float4 index in [0, 2048)
        int r = i >> 4, f = i & 15;
        float4 a = ((const float4*)g_acc)[(q0 + r)*16 + f];
        float4 vc = *(const float4*)&vcol[f*4];
        float inv = 1.0f / rs_s[r];
        float hv[4] = {(a.x+vc.x)*inv, (a.y+vc.y)*inv, (a.z+vc.z)*inv, (a.w+vc.w)*inv};
        if (sy == 0)
            ((float4*)g_h)[(q0 + r)*16 + f] = make_float4(hv[0], hv[1], hv[2], hv[3]);
        float hi[4], lo[4];
        #pragma unroll
        for (int e = 0; e < 4; e++) {
            __nv_bfloat16 h = __float2bfloat16(hv[e]);
            hi[e] = __bfloat162float(h);
            lo[e] = hv[e] - hi[e];
        }
        int col = f*4;
        *(uint32_t*)&Fh[r*LDK + col]     = packbf2(hi[0], hi[1]);
        *(uint32_t*)&Fh[r*LDK + col + 2] = packbf2(hi[2], hi[3]);
        *(uint32_t*)&Fl[r*LDK + col]     = packbf2(lo[0], lo[1]);
        *(uint32_t*)&Fl[r*LDK + col + 2] = packbf2(lo[2], lo[3]);
    }
    __syncthreads();

    uint32_t fha[2][4][4], fla[2][4][4];
    #pragma unroll
    for (int mi = 0; mi < 2; mi++)
        #pragma unroll
        for (int ks = 0; ks < 4; ks++) {
            int row = wm*32 + mi*16 + (lane & 15);
            ldsm_x4(smaddr(Fh + row*LDK + ks*16 + (lane >> 4)*8),
                    fha[mi][ks][0], fha[mi][ks][1], fha[mi][ks][2], fha[mi][ks][3]);
            ldsm_x4(smaddr(Fl + row*LDK + ks*16 + (lane >> 4)*8),
                    fla[mi][ks][0], fla[mi][ks][1], fla[mi][ks][2], fla[mi][ks][3]);
        }

    float best[2][2];
    int   bidx[2][2];
    #pragma unroll
    for (int mi = 0; mi < 2; mi++)
        #pragma unroll
        for (int h = 0; h < 2; h++) { best[mi][h] = 3.4e38f; bidx[mi][h] = 0; }

    for (int t = 0; t < Kc/VQS/128; t++) {   // 2 tiles
        __syncthreads();
        const int c0 = (kbase + t*128)*64;
        for (int c = tid; c < 1024; c += 256) {
            int r = c >> 3, g = c & 7;
            cpa16(smaddr(Ch + r*LDK + g*8), g_cbh + c0 + r*64 + g*8);
            cpa16(smaddr(Cl + r*LDK + g*8), g_cbl + c0 + r*64 + g*8);
        }
        asm volatile("cp.async.commit_group;");
        asm volatile("cp.async.wait_group 0;");
        __syncthreads();

        float c[2][8][4] = {};
        #pragma unroll
        for (int nj = 0; nj < 8; nj++) {
            uint32_t chb[4][2], clb[4][2];
            int r = wn*64 + nj*8 + (lane & 7);
            ldsm_x4(smaddr(Ch + r*LDK + (lane >> 3)*8),
                    chb[0][0], chb[0][1], chb[1][0], chb[1][1]);
            ldsm_x4(smaddr(Ch + r*LDK + 32 + (lane >> 3)*8),
                    chb[2][0], chb[2][1], chb[3][0], chb[3][1]);
            ldsm_x4(smaddr(Cl + r*LDK + (lane >> 3)*8),
                    clb[0][0], clb[0][1], clb[1][0], clb[1][1]);
            ldsm_x4(smaddr(Cl + r*LDK + 32 + (lane >> 3)*8),
                    clb[2][0], clb[2][1], clb[3][0], clb[3][1]);
            #pragma unroll
            for (int mi = 0; mi < 2; mi++)
                #pragma unroll
                for (int ks = 0; ks < 4; ks++) {
                    mma16816(c[mi][nj], fha[mi][ks], chb[ks][0], chb[ks][1]);
                    mma16816(c[mi][nj], fla[mi][ks], chb[ks][0], chb[ks][1]);
                    mma16816(c[mi][nj], fha[mi][ks], clb[ks][0], clb[ks][1]);
                }
        }

        // ascending col order per thread -> '<' keeps first (lowest) index
        #pragma unroll
        for (int mi = 0; mi < 2; mi++)
            #pragma unroll
            for (int nj = 0; nj < 8; nj++)
                #pragma unroll
                for (int e = 0; e < 4; e++) {
                    int lcol = t*128 + wn*64 + nj*8 + (lane & 3)*2 + (e & 1);
                    float d2 = cns[lcol] - 2.0f * c[mi][nj][e];
                    int h = e >> 1;
                    if (d2 < best[mi][h]) { best[mi][h] = d2; bidx[mi][h] = kbase + lcol; }
                }
    }

    #pragma unroll
    for (int mi = 0; mi < 2; mi++)
        #pragma unroll
        for (int h = 0; h < 2; h++) {
            float v = best[mi][h]; int ix = bidx[mi][h];
            #pragma unroll
            for (int off = 1; off <= 2; off <<= 1) {
                float v2 = __shfl_xor_sync(0xffffffffu, v, off);
                int   i2 = __shfl_xor_sync(0xffffffffu, ix, off);
                if (v2 < v || (v2 == v && i2 < ix)) { v = v2; ix = i2; }
            }
            if ((lane & 3) == 0) {
                int row = wm*32 + mi*16 + h*8 + (lane >> 2);
                redv[wn*128 + row] = v;
                redi[wn*128 + row] = ix;
            }
        }
    __syncthreads();
    if (tid < 128) {
        float v0 = redv[tid], v1 = redv[128 + tid];
        int   i0 = redi[tid], i1 = redi[128 + tid];
        bool take1 = (v1 < v0) || (v1 == v0 && i1 < i0);
        g_bval[sy][q0 + tid] = take1 ? v1 : v0;
        g_bidx[sy][q0 + tid] = take1 ? i1 : i0;
    }
}

// ---------------------------------------------------------------------------
// 5. merge VQ splits + per-batch means + final projection.
//    Phase 1: 50 threads merge splits (1 row each, branchless) -> smem idx.
//    Phase 2: gather with address-independent, predicated unrolled loop
//    (high MLP: ~26 outstanding loads per thread).
// ---------------------------------------------------------------------------
__global__ void __launch_bounds__(256) final_kernel(
    const float* __restrict__ cb, const float* __restrict__ W_enc,
    const float* __restrict__ b_enc, float* __restrict__ out)
{
    const int b = blockIdx.x, tid = threadIdx.x;
    const int d = tid & 63, grp = tid >> 6;    // 4 groups of 64
    __shared__ int   sidx[Ll];
    __shared__ float sv[4*64], sh2[4*64], x[2*Dd];

    // phase 1: branchless split merge, one row per thread
    if (tid < Ll) {
        int n = b*Ll + tid;
        float bv = g_bval[0][n]; int bi = g_bidx[0][n];
        #pragma unroll
        for (int sp = 1; sp < VQS; sp++) {
            float v = g_bval[sp][n];
            int   j = g_bidx[sp][n];
            bool  t = v < bv;            // strict '<': first-index tie-break
            bv = t ? v : bv;
            bi = t ? j : bi;
        }
        sidx[tid] = bi;
    }
    __syncthreads();

    // phase 2: independent gathers (predicated fixed-trip loop -> MLP)
    float vs = 0.0f, hs = 0.0f;
    #pragma unroll
    for (int it = 0; it < 13; it++) {
        int l = grp + it*4;
        if (l < Ll) {
            vs += cb[(size_t)sidx[l]*Dd + d];
            hs += g_h[(b*Ll + l)*Dd + d];
        }
    }
    sv[grp*64 + d] = vs;
    sh2[grp*64 + d] = hs;
    __syncthreads();
    if (tid < 64) {
        float den = g_denom[b];
        float v  = sv[tid] + sv[64 + tid] + sv[128 + tid] + sv[192 + tid];
        float hh = sh2[tid] + sh2[64 + tid] + sh2[128 + tid] + sh2[192 + tid];
        x[tid]      = v / den;
        x[Dd + tid] = hh / (den + 1e-9f);
    }
    __syncthreads();
    if (tid < 64) {
        float a0 = b_enc[d], a1 = 0.f, a2 = 0.f, a3 = 0.f;
        #pragma unroll 8
        for (int i = 0; i < 2*Dd; i += 4) {
            a0 = fmaf(x[i],     W_enc[i*Dd + d],       a0);
            a1 = fmaf(x[i + 1], W_enc[(i + 1)*Dd + d], a1);
            a2 = fmaf(x[i + 2], W_enc[(i + 2)*Dd + d], a2);
            a3 = fmaf(x[i + 3], W_enc[(i + 3)*Dd + d], a3);
        }
        out[b*Dd + d] = (a0 + a1) + (a2 + a3);
    }
}

// ---------------------------------------------------------------------------
extern "C" void kernel_launch(void* const* d_in, const int* in_sizes, int n_in,
                              void* d_out, int out_size) {
    const int*   ids   = (const int*)d_in[0];
    const int*   masks = (const int*)d_in[1];
    const float* emb   = (const float*)d_in[2];
    const float* cb    = (const float*)d_in[3];
    const float* Wq    = (const float*)d_in[4];
    const float* bq    = (const float*)d_in[5];
    const float* Wk    = (const float*)d_in[6];
    const float* bk    = (const float*)d_in[7];
    const float* Wv    = (const float*)d_in[8];
    const float* bv    = (const float*)d_in[9];
    const float* W_enc = (const float*)d_in[10];
    const float* b_enc = (const float*)d_in[11];
    float* out = (float*)d_out;

    cudaFuncSetAttribute((const void*)qkv_tc_kernel,
                         cudaFuncAttributeMaxDynamicSharedMemorySize, QKV_SMEM_B);
    cudaFuncSetAttribute((const void*)attn_tc_kernel,
                         cudaFuncAttributeMaxDynamicSharedMemorySize, ATTN_SMEM_B);
    cudaFuncSetAttribute((const void*)vq_tc_kernel,
                         cudaFuncAttributeMaxDynamicSharedMemorySize, VQ_SMEM_B);

    prep_kernel<<<172, 256>>>(masks, cb);
    qkv_tc_kernel<<<dim3(Nn/128, 3), 256, QKV_SMEM_B>>>(ids, masks, emb,
                                                        Wq, bq, Wk, bk, Wv, bv);
    attn_tc_kernel<<<dim3(Nn/128, 6), 256, ATTN_SMEM_B>>>();
    vq_tc_kernel<<<dim3(Nn/128, VQS), 256, VQ_SMEM_B>>>();
    final_kernel<<<Bb, 256>>>(cb, W_enc, b_enc, out);
}